// round 2
// baseline (speedup 1.0000x reference)
#include <cuda_runtime.h>
#include <math.h>

typedef unsigned long long u64t;

#define EM1 4
#define NN 64
#define FF 32
#define U1C 128
#define U2C 64
#define UAC 128
#define NT 512
#define BATCH 2048

// shared memory layout (float offsets); pads chosen for bank-conflict-free access
#define ADJ_PITCH 65
#define NODE_PITCH 34
#define H1_PITCH 130
#define AN_PITCH 34
#define P2_PITCH 66
#define H2_PITCH 66   // FIXED: was 34, but h2 has U2=64 columns -> rows were overlapping

#define OFF_ADJ 0
#define OFF_NODE (OFF_ADJ + EM1*NN*ADJ_PITCH)          // 16640
#define OFF_RS   (OFF_NODE + NN*NODE_PITCH)            // 18816
#define OFF_H1   (OFF_RS + EM1*NN)                     // 19072
#define OFF_U    (OFF_H1 + NN*H1_PITCH)                // 27392 (an[4][64][34] / pre2[4][64][66] union)
#define OFF_H2   (OFF_U + EM1*NN*P2_PITCH)             // 44288
#define OFF_RED  (OFF_H2 + NN*H2_PITCH)                // 48512
#define SMEM_FLOATS (OFF_RED + 4*UAC)                  // 49024
#define SMEM_BYTES (SMEM_FLOATS * 4)                   // 196096 B

// ---- packed fp32x2 helpers (Blackwell f32x2 pipe: 2x FFMA rate) ----
__device__ __forceinline__ u64t ffma2(u64t acc, u64t w, u64t a2) {
    u64t r;
    asm("fma.rn.f32x2 %0, %1, %2, %3;" : "=l"(r) : "l"(w), "l"(a2), "l"(acc));
    return r;
}
__device__ __forceinline__ u64t splat2(float a) {
    u64t r; asm("mov.b64 %0, {%1, %1};" : "=l"(r) : "f"(a)); return r;
}
__device__ __forceinline__ float2 unpack2(u64t v) {
    float2 f; asm("mov.b64 {%0, %1}, %2;" : "=f"(f.x), "=f"(f.y) : "l"(v)); return f;
}
__device__ __forceinline__ float sigmoidf_(float x) { return 1.0f / (1.0f + expf(-x)); }

__global__ void __launch_bounds__(NT, 1)
encoder_kernel(const float* __restrict__ adjacency,
               const float* __restrict__ node,
               const float* __restrict__ W1, const float* __restrict__ b1,
               const float* __restrict__ V1, const float* __restrict__ c1,
               const float* __restrict__ W2, const float* __restrict__ b2,
               const float* __restrict__ V2, const float* __restrict__ c2,
               const float* __restrict__ Wi, const float* __restrict__ bi,
               const float* __restrict__ Wj, const float* __restrict__ bj,
               float* __restrict__ out)
{
    extern __shared__ float smem[];
    const int b = blockIdx.x;
    const int tid = threadIdx.x;

    // ---------------- Phase A: stage adjacency (transposed, drop edge-type 0) + node ----
    {
        const float* adjB = adjacency + (size_t)b * (NN * NN * 5);
        for (int idx = tid; idx < NN * NN * 5; idx += NT) {
            float v = adjB[idx];
            int e = idx % 5;
            int r = idx / 5;           // r = m*64 + n
            if (e > 0)
                smem[OFF_ADJ + ((e - 1) * NN + (r >> 6)) * ADJ_PITCH + (r & 63)] = v;
        }
        const float* nodeB = node + (size_t)b * (NN * FF);
        for (int idx = tid; idx < NN * FF; idx += NT)
            smem[OFF_NODE + (idx >> 5) * NODE_PITCH + (idx & 31)] = nodeB[idx];
    }
    __syncthreads();

    // ---------------- Phase B: an[e][m][f] = adj_e @ node ; rowsum[e][m] -----------------
    {
        const int pair = tid >> 1;           // 0..255
        const int e = pair >> 6;
        const int m = pair & 63;
        const int fh = tid & 1;
        const int f0 = fh * 16;              // 16 f's per thread = 8 f32x2
        u64t acc[8];
        #pragma unroll
        for (int i = 0; i < 8; i++) acc[i] = 0ull;
        float rs = 0.0f;
        const float* adjr = &smem[OFF_ADJ + (e * NN + m) * ADJ_PITCH];
        #pragma unroll 4
        for (int n = 0; n < NN; n++) {
            float a = adjr[n];
            rs += a;
            u64t a2 = splat2(a);
            const u64t* np = (const u64t*)&smem[OFF_NODE + n * NODE_PITCH + f0];
            #pragma unroll
            for (int i = 0; i < 8; i++) acc[i] = ffma2(acc[i], np[i], a2);
        }
        u64t* dst = (u64t*)&smem[OFF_U + (e * NN + m) * AN_PITCH + f0];
        #pragma unroll
        for (int i = 0; i < 8; i++) dst[i] = acc[i];
        if (fh == 0) smem[OFF_RS + e * NN + m] = rs;
    }
    __syncthreads();

    // ---------------- Phase C: h1[m][u] = tanh(sum_e an_e@W1_e + rowsum_e*b1_e + node@V1 + c1)
    {
        const int m0 = (tid >> 5) * 4;       // warp-uniform: 4 m's
        const int uc = tid & 31;
        const int u0 = uc * 4;               // 4 u's = 2 f32x2
        u64t acc[4][2];
        const u64t* c1p = (const u64t*)(c1 + u0);
        u64t ci0 = c1p[0], ci1 = c1p[1];
        #pragma unroll
        for (int im = 0; im < 4; im++) { acc[im][0] = ci0; acc[im][1] = ci1; }

        #pragma unroll 1
        for (int e = 0; e < EM1; e++) {
            const float* anb = &smem[OFF_U + (e * NN + m0) * AN_PITCH];
            const float* w1b = W1 + e * FF * U1C + u0;
            #pragma unroll 4
            for (int f = 0; f < FF; f++) {
                const u64t* wp = (const u64t*)(w1b + f * U1C);
                u64t w0 = wp[0], w1v = wp[1];
                #pragma unroll
                for (int im = 0; im < 4; im++) {
                    u64t a2 = splat2(anb[im * AN_PITCH + f]);
                    acc[im][0] = ffma2(acc[im][0], w0, a2);
                    acc[im][1] = ffma2(acc[im][1], w1v, a2);
                }
            }
        }
        #pragma unroll
        for (int e = 0; e < EM1; e++) {      // b1 weighted by adjacency row sums
            const u64t* bp = (const u64t*)(b1 + e * U1C + u0);
            u64t w0 = bp[0], w1v = bp[1];
            #pragma unroll
            for (int im = 0; im < 4; im++) {
                u64t a2 = splat2(smem[OFF_RS + e * NN + m0 + im]);
                acc[im][0] = ffma2(acc[im][0], w0, a2);
                acc[im][1] = ffma2(acc[im][1], w1v, a2);
            }
        }
        #pragma unroll 4
        for (int f = 0; f < FF; f++) {       // node @ V1
            const u64t* wp = (const u64t*)(V1 + f * U1C + u0);
            u64t w0 = wp[0], w1v = wp[1];
            #pragma unroll
            for (int im = 0; im < 4; im++) {
                u64t a2 = splat2(smem[OFF_NODE + (m0 + im) * NODE_PITCH + f]);
                acc[im][0] = ffma2(acc[im][0], w0, a2);
                acc[im][1] = ffma2(acc[im][1], w1v, a2);
            }
        }
        #pragma unroll
        for (int im = 0; im < 4; im++) {
            float* h1r = &smem[OFF_H1 + (m0 + im) * H1_PITCH + u0];
            float2 x0 = unpack2(acc[im][0]);
            float2 x1 = unpack2(acc[im][1]);
            h1r[0] = tanhf(x0.x); h1r[1] = tanhf(x0.y);
            h1r[2] = tanhf(x1.x); h1r[3] = tanhf(x1.y);
        }
    }
    __syncthreads();

    // ---------------- Phase D: pre2[e][n][u] = [h1,node][n] @ W2[e] + b2[e] ---------------
    {
        const int e = tid >> 7;
        const int r = tid & 127;
        const int n0 = (r >> 4) * 8;         // 8 n's
        const int uc = r & 15;
        const int u0 = uc * 4;               // 4 u's
        u64t acc[8][2];
        const u64t* b2p = (const u64t*)(b2 + e * U2C + u0);
        u64t bb0 = b2p[0], bb1 = b2p[1];
        #pragma unroll
        for (int in = 0; in < 8; in++) { acc[in][0] = bb0; acc[in][1] = bb1; }

        const float* w2b = W2 + e * (U1C + FF) * U2C + u0;
        #pragma unroll 2
        for (int k = 0; k < U1C; k++) {
            const u64t* wp = (const u64t*)(w2b + k * U2C);
            u64t w0 = wp[0], w1v = wp[1];
            #pragma unroll
            for (int in = 0; in < 8; in++) {
                u64t a2 = splat2(smem[OFF_H1 + (n0 + in) * H1_PITCH + k]);
                acc[in][0] = ffma2(acc[in][0], w0, a2);
                acc[in][1] = ffma2(acc[in][1], w1v, a2);
            }
        }
        #pragma unroll 2
        for (int k = 0; k < FF; k++) {
            const u64t* wp = (const u64t*)(w2b + (U1C + k) * U2C);
            u64t w0 = wp[0], w1v = wp[1];
            #pragma unroll
            for (int in = 0; in < 8; in++) {
                u64t a2 = splat2(smem[OFF_NODE + (n0 + in) * NODE_PITCH + k]);
                acc[in][0] = ffma2(acc[in][0], w0, a2);
                acc[in][1] = ffma2(acc[in][1], w1v, a2);
            }
        }
        #pragma unroll
        for (int in = 0; in < 8; in++) {
            u64t* dst = (u64t*)&smem[OFF_U + (e * NN + n0 + in) * P2_PITCH + u0];
            dst[0] = acc[in][0]; dst[1] = acc[in][1];
        }
    }
    __syncthreads();

    // ---------------- Phase E: h2[m][u] = tanh(sum_e adj_e @ pre2_e + node@V2 + c2) -------
    {
        const int m0 = (tid >> 4) * 2;       // 2 m's
        const int uc = tid & 15;
        const int u0 = uc * 4;
        u64t acc[2][2];
        const u64t* c2p = (const u64t*)(c2 + u0);
        acc[0][0] = c2p[0]; acc[0][1] = c2p[1];
        acc[1][0] = c2p[0]; acc[1][1] = c2p[1];

        #pragma unroll 1
        for (int e = 0; e < EM1; e++) {
            const float* adj0 = &smem[OFF_ADJ + (e * NN + m0) * ADJ_PITCH];
            const float* adj1 = adj0 + ADJ_PITCH;
            const float* p2b = &smem[OFF_U + e * NN * P2_PITCH + u0];
            #pragma unroll 4
            for (int n = 0; n < NN; n++) {
                const u64t* wp = (const u64t*)(p2b + n * P2_PITCH);
                u64t w0 = wp[0], w1v = wp[1];
                u64t a0 = splat2(adj0[n]);
                u64t a1 = splat2(adj1[n]);
                acc[0][0] = ffma2(acc[0][0], w0, a0);
                acc[0][1] = ffma2(acc[0][1], w1v, a0);
                acc[1][0] = ffma2(acc[1][0], w0, a1);
                acc[1][1] = ffma2(acc[1][1], w1v, a1);
            }
        }
        #pragma unroll 4
        for (int f = 0; f < FF; f++) {       // node @ V2
            const u64t* wp = (const u64t*)(V2 + f * U2C + u0);
            u64t w0 = wp[0], w1v = wp[1];
            u64t a0 = splat2(smem[OFF_NODE + m0 * NODE_PITCH + f]);
            u64t a1 = splat2(smem[OFF_NODE + (m0 + 1) * NODE_PITCH + f]);
            acc[0][0] = ffma2(acc[0][0], w0, a0);
            acc[0][1] = ffma2(acc[0][1], w1v, a0);
            acc[1][0] = ffma2(acc[1][0], w0, a1);
            acc[1][1] = ffma2(acc[1][1], w1v, a1);
        }
        #pragma unroll
        for (int im = 0; im < 2; im++) {
            float* h2r = &smem[OFF_H2 + (m0 + im) * H2_PITCH + u0];
            float2 x0 = unpack2(acc[im][0]);
            float2 x1 = unpack2(acc[im][1]);
            h2r[0] = tanhf(x0.x); h2r[1] = tanhf(x0.y);
            h2r[2] = tanhf(x1.x); h2r[3] = tanhf(x1.y);
        }
    }
    __syncthreads();

    // ---------------- Phase F: gates, prod[n][u] = sigmoid(ann@Wi+bi)*tanh(ann@Wj+bj) -----
    {
        const int n0 = (tid >> 5) * 4;       // warp-uniform: 4 n's
        const int uc = tid & 31;
        const int u0 = uc * 4;
        u64t ai[4][2], aj[4][2];
        const u64t* bip = (const u64t*)(bi + u0);
        const u64t* bjp = (const u64t*)(bj + u0);
        u64t bi0 = bip[0], bi1 = bip[1], bj0 = bjp[0], bj1 = bjp[1];
        #pragma unroll
        for (int in = 0; in < 4; in++) {
            ai[in][0] = bi0; ai[in][1] = bi1;
            aj[in][0] = bj0; aj[in][1] = bj1;
        }
        #pragma unroll 2
        for (int k = 0; k < U2C; k++) {
            const u64t* wip = (const u64t*)(Wi + k * UAC + u0);
            const u64t* wjp = (const u64t*)(Wj + k * UAC + u0);
            u64t wi0 = wip[0], wi1 = wip[1];
            u64t wj0 = wjp[0], wj1 = wjp[1];
            #pragma unroll
            for (int in = 0; in < 4; in++) {
                u64t a2 = splat2(smem[OFF_H2 + (n0 + in) * H2_PITCH + k]);
                ai[in][0] = ffma2(ai[in][0], wi0, a2);
                ai[in][1] = ffma2(ai[in][1], wi1, a2);
                aj[in][0] = ffma2(aj[in][0], wj0, a2);
                aj[in][1] = ffma2(aj[in][1], wj1, a2);
            }
        }
        #pragma unroll 2
        for (int k = 0; k < FF; k++) {
            const u64t* wip = (const u64t*)(Wi + (U2C + k) * UAC + u0);
            const u64t* wjp = (const u64t*)(Wj + (U2C + k) * UAC + u0);
            u64t wi0 = wip[0], wi1 = wip[1];
            u64t wj0 = wjp[0], wj1 = wjp[1];
            #pragma unroll
            for (int in = 0; in < 4; in++) {
                u64t a2 = splat2(smem[OFF_NODE + (n0 + in) * NODE_PITCH + k]);
                ai[in][0] = ffma2(ai[in][0], wi0, a2);
                ai[in][1] = ffma2(ai[in][1], wi1, a2);
                aj[in][0] = ffma2(aj[in][0], wj0, a2);
                aj[in][1] = ffma2(aj[in][1], wj1, a2);
            }
        }
        #pragma unroll
        for (int in = 0; in < 4; in++) {     // prod stored into (dead) h1 region
            float* pr = &smem[OFF_H1 + (n0 + in) * H1_PITCH + u0];
            float2 xi0 = unpack2(ai[in][0]), xi1 = unpack2(ai[in][1]);
            float2 xj0 = unpack2(aj[in][0]), xj1 = unpack2(aj[in][1]);
            pr[0] = sigmoidf_(xi0.x) * tanhf(xj0.x);
            pr[1] = sigmoidf_(xi0.y) * tanhf(xj0.y);
            pr[2] = sigmoidf_(xi1.x) * tanhf(xj1.x);
            pr[3] = sigmoidf_(xi1.y) * tanhf(xj1.y);
        }
    }
    __syncthreads();

    // ---------------- Phase G: out[b][u] = tanh(sum_n prod[n][u]) --------------------------
    {
        const int q = tid >> 7;              // 0..3
        const int u = tid & 127;
        float s = 0.0f;
        #pragma unroll
        for (int i = 0; i < 16; i++)
            s += smem[OFF_H1 + (q * 16 + i) * H1_PITCH + u];
        smem[OFF_RED + q * UAC + u] = s;
    }
    __syncthreads();
    if (tid < UAC) {
        float s = smem[OFF_RED + tid] + smem[OFF_RED + UAC + tid]
                + smem[OFF_RED + 2 * UAC + tid] + smem[OFF_RED + 3 * UAC + tid];
        out[(size_t)b * UAC + tid] = tanhf(s);
    }
}

extern "C" void kernel_launch(void* const* d_in, const int* in_sizes, int n_in,
                              void* d_out, int out_size) {
    (void)in_sizes; (void)n_in; (void)out_size;
    const float* adjacency = (const float*)d_in[0];
    // d_in[1] = hidden (rank-2, unused by the encoder math)
    const float* node = (const float*)d_in[2];
    const float* W1 = (const float*)d_in[3];
    const float* b1 = (const float*)d_in[4];
    const float* V1 = (const float*)d_in[5];
    const float* c1 = (const float*)d_in[6];
    const float* W2 = (const float*)d_in[7];
    const float* b2 = (const float*)d_in[8];
    const float* V2 = (const float*)d_in[9];
    const float* c2 = (const float*)d_in[10];
    const float* Wi = (const float*)d_in[11];
    const float* bi = (const float*)d_in[12];
    const float* Wj = (const float*)d_in[13];
    const float* bj = (const float*)d_in[14];

    cudaFuncSetAttribute(encoder_kernel,
                         cudaFuncAttributeMaxDynamicSharedMemorySize, SMEM_BYTES);
    encoder_kernel<<<BATCH, NT, SMEM_BYTES>>>(adjacency, node,
                                              W1, b1, V1, c1,
                                              W2, b2, V2, c2,
                                              Wi, bi, Wj, bj,
                                              (float*)d_out);
}